// round 1
// baseline (speedup 1.0000x reference)
#include <cuda_runtime.h>
#include <cuda_bf16.h>

// ---------------- static problem config ----------------
#define T 4096      // tokens (B*S)
#define H 1024      // hidden
#define F 2048      // ffn
#define E 32        // experts
#define KSEL 2      // top-k
#define CAP 512     // expert capacity
#define AUX_COEF 0.01f

// ---------------- device scratch (no allocs allowed) ----------------
__device__ float g_probs[T * E];          // router softmax probs
__device__ int   g_top1[T];               // argmax expert per token
__device__ int   g_route_e[T * KSEL];     // expert per slot
__device__ float g_route_w[T * KSEL];     // renormalized weight per slot
__device__ int   g_route_pos[T * KSEL];   // slot within expert (may be >= CAP)
__device__ int   g_route_keep[T * KSEL];  // pos < CAP
__device__ int   g_count[E];              // kept rows per expert
__device__ float g_buf[(size_t)E * CAP * H];   // 64 MB dispatch buffer
__device__ float g_hid[(size_t)E * CAP * F];   // 128 MB silu(g)*u
__device__ float g_y[(size_t)E * CAP * H];     // 64 MB expert output

// ---------------- router: logits, softmax, top-2, weights ----------------
__global__ void router_kernel(const float* __restrict__ x,
                              const float* __restrict__ Wr,
                              const float* __restrict__ br) {
    int t = blockIdx.x;
    __shared__ float xs[H];
    __shared__ float sl[E];
    int tid = threadIdx.x;
    for (int h = tid; h < H; h += 256) xs[h] = x[(size_t)t * H + h];
    __syncthreads();

    // 8 threads per expert
    int e = tid >> 3, r = tid & 7;
    float acc = 0.f;
    const float* w = Wr + (size_t)e * H;
    for (int h = r; h < H; h += 8) acc += xs[h] * w[h];
    acc += __shfl_down_sync(0xffffffffu, acc, 4, 8);
    acc += __shfl_down_sync(0xffffffffu, acc, 2, 8);
    acc += __shfl_down_sync(0xffffffffu, acc, 1, 8);
    if (r == 0) sl[e] = acc + br[e];
    __syncthreads();

    if (tid < 32) {
        float l = sl[tid];
        float m = l;
        #pragma unroll
        for (int o = 16; o; o >>= 1) m = fmaxf(m, __shfl_xor_sync(0xffffffffu, m, o));
        float p = __expf(l - m);
        float s = p;
        #pragma unroll
        for (int o = 16; o; o >>= 1) s += __shfl_xor_sync(0xffffffffu, s, o);
        p = p / s;
        g_probs[(size_t)t * E + tid] = p;

        // top-1 with lowest-index tie-break
        float p1 = p; int i1 = tid;
        #pragma unroll
        for (int o = 16; o; o >>= 1) {
            float op = __shfl_xor_sync(0xffffffffu, p1, o);
            int   oi = __shfl_xor_sync(0xffffffffu, i1, o);
            if (op > p1 || (op == p1 && oi < i1)) { p1 = op; i1 = oi; }
        }
        // top-2: mask out winner
        float pm = (tid == i1) ? -1.f : p;
        float p2 = pm; int i2 = tid;
        #pragma unroll
        for (int o = 16; o; o >>= 1) {
            float op = __shfl_xor_sync(0xffffffffu, p2, o);
            int   oi = __shfl_xor_sync(0xffffffffu, i2, o);
            if (op > p2 || (op == p2 && oi < i2)) { p2 = op; i2 = oi; }
        }
        if (tid == 0) {
            g_top1[t] = i1;
            float mx = fmaxf(p1, p2);
            float e1 = __expf(p1 - mx), e2 = __expf(p2 - mx);
            float inv = 1.f / (e1 + e2);
            g_route_e[2 * t]     = i1; g_route_w[2 * t]     = e1 * inv;
            g_route_e[2 * t + 1] = i2; g_route_w[2 * t + 1] = e2 * inv;
        }
    }
}

// ---------------- dispatch: order-preserving per-expert prefix scan ----------------
__global__ void dispatch_kernel() {
    int warp = threadIdx.x >> 5, lane = threadIdx.x & 31;
    int base = 0;
    for (int c = 0; c < T * KSEL; c += 32) {
        int e = g_route_e[c + lane];
        unsigned m = __ballot_sync(0xffffffffu, e == warp);
        if (e == warp) {
            int pos = base + __popc(m & ((1u << lane) - 1u));
            g_route_pos[c + lane]  = pos;
            g_route_keep[c + lane] = (pos < CAP) ? 1 : 0;
        }
        base += __popc(m);
    }
    if (lane == 0) g_count[warp] = (base < CAP) ? base : CAP;
}

// ---------------- gather kept tokens into [E, CAP, H] ----------------
__global__ void gather_kernel(const float* __restrict__ x) {
    int i = blockIdx.x;
    if (!g_route_keep[i]) return;
    int t = i >> 1;
    int e = g_route_e[i], pos = g_route_pos[i];
    float* dst = g_buf + ((size_t)e * CAP + pos) * H;
    const float* src = x + (size_t)t * H;
    for (int h = threadIdx.x; h < H; h += 256) dst[h] = src[h];
}

// ---------------- fused gate/up GEMM + SwiGLU epilogue ----------------
// C[m,n] = silu(A@Wg)[m,n] * (A@Wu)[m,n]   A:[cnt,H]  Wg,Wu:[H,F]
#define BM 64
#define BN 64
#define BK 16
__global__ void gu_kernel(const float* __restrict__ Wg,
                          const float* __restrict__ Wu) {
    int e = blockIdx.z;
    int cnt = g_count[e];
    int m0 = blockIdx.y * BM;
    if (m0 >= cnt) return;
    int n0 = blockIdx.x * BN;

    __shared__ float As[BK][BM];
    __shared__ float Bg[BK][BN];
    __shared__ float Bu[BK][BN];

    const float* A = g_buf + (size_t)e * CAP * H;
    const float* G = Wg + (size_t)e * H * F;
    const float* U = Wu + (size_t)e * H * F;

    int tid = threadIdx.x;
    int tx = tid & 15, ty = tid >> 4;

    float accg[4][4] = {};
    float accu[4][4] = {};

    for (int k0 = 0; k0 < H; k0 += BK) {
        for (int i = tid; i < BM * BK; i += 256) {
            int m = i >> 4, k = i & 15;
            int gm = m0 + m;
            As[k][m] = (gm < cnt) ? A[(size_t)gm * H + k0 + k] : 0.f;
        }
        for (int i = tid; i < BK * BN; i += 256) {
            int k = i >> 6, n = i & 63;
            size_t off = (size_t)(k0 + k) * F + n0 + n;
            Bg[k][n] = G[off];
            Bu[k][n] = U[off];
        }
        __syncthreads();
        #pragma unroll
        for (int k = 0; k < BK; k++) {
            float a[4], bg[4], bu[4];
            #pragma unroll
            for (int i = 0; i < 4; i++) a[i] = As[k][ty * 4 + i];
            #pragma unroll
            for (int j = 0; j < 4; j++) { bg[j] = Bg[k][tx * 4 + j]; bu[j] = Bu[k][tx * 4 + j]; }
            #pragma unroll
            for (int i = 0; i < 4; i++)
                #pragma unroll
                for (int j = 0; j < 4; j++) {
                    accg[i][j] = fmaf(a[i], bg[j], accg[i][j]);
                    accu[i][j] = fmaf(a[i], bu[j], accu[i][j]);
                }
        }
        __syncthreads();
    }

    float* Hd = g_hid + (size_t)e * CAP * F;
    #pragma unroll
    for (int i = 0; i < 4; i++) {
        int gm = m0 + ty * 4 + i;
        if (gm >= cnt) continue;
        #pragma unroll
        for (int j = 0; j < 4; j++) {
            float g = accg[i][j], u = accu[i][j];
            float sv = g / (1.f + __expf(-g));
            Hd[(size_t)gm * F + n0 + tx * 4 + j] = sv * u;
        }
    }
}

// ---------------- down GEMM: y = hid @ Wd   hid:[cnt,F] Wd:[F,H] ----------------
__global__ void down_kernel(const float* __restrict__ Wd) {
    int e = blockIdx.z;
    int cnt = g_count[e];
    int m0 = blockIdx.y * BM;
    if (m0 >= cnt) return;
    int n0 = blockIdx.x * BN;

    __shared__ float As[BK][BM];
    __shared__ float Bs[BK][BN];

    const float* A = g_hid + (size_t)e * CAP * F;
    const float* B = Wd + (size_t)e * F * H;

    int tid = threadIdx.x;
    int tx = tid & 15, ty = tid >> 4;
    float acc[4][4] = {};

    for (int k0 = 0; k0 < F; k0 += BK) {
        for (int i = tid; i < BM * BK; i += 256) {
            int m = i >> 4, k = i & 15;
            int gm = m0 + m;
            As[k][m] = (gm < cnt) ? A[(size_t)gm * F + k0 + k] : 0.f;
        }
        for (int i = tid; i < BK * BN; i += 256) {
            int k = i >> 6, n = i & 63;
            Bs[k][n] = B[(size_t)(k0 + k) * H + n0 + n];
        }
        __syncthreads();
        #pragma unroll
        for (int k = 0; k < BK; k++) {
            float a[4], b[4];
            #pragma unroll
            for (int i = 0; i < 4; i++) a[i] = As[k][ty * 4 + i];
            #pragma unroll
            for (int j = 0; j < 4; j++) b[j] = Bs[k][tx * 4 + j];
            #pragma unroll
            for (int i = 0; i < 4; i++)
                #pragma unroll
                for (int j = 0; j < 4; j++)
                    acc[i][j] = fmaf(a[i], b[j], acc[i][j]);
        }
        __syncthreads();
    }

    float* Y = g_y + (size_t)e * CAP * H;
    #pragma unroll
    for (int i = 0; i < 4; i++) {
        int gm = m0 + ty * 4 + i;
        if (gm >= cnt) continue;
        #pragma unroll
        for (int j = 0; j < 4; j++)
            Y[(size_t)gm * H + n0 + tx * 4 + j] = acc[i][j];
    }
}

// ---------------- combine: weighted sum of the 2 expert rows ----------------
__global__ void combine_kernel(float* __restrict__ out) {
    int t = blockIdx.x;
    int i0 = 2 * t, i1 = 2 * t + 1;
    int e0 = g_route_e[i0], e1 = g_route_e[i1];
    int k0 = g_route_keep[i0], k1 = g_route_keep[i1];
    int p0 = k0 ? g_route_pos[i0] : 0;
    int p1 = k1 ? g_route_pos[i1] : 0;
    float w0 = k0 ? g_route_w[i0] : 0.f;
    float w1 = k1 ? g_route_w[i1] : 0.f;
    const float* y0 = g_y + ((size_t)e0 * CAP + p0) * H;
    const float* y1 = g_y + ((size_t)e1 * CAP + p1) * H;
    float* o = out + (size_t)t * H;
    for (int h = threadIdx.x; h < H; h += 256)
        o[h] = w0 * y0[h] + w1 * y1[h];
}

// ---------------- aux loss ----------------
__global__ void aux_kernel(float* __restrict__ out_aux) {
    int e = threadIdx.x >> 5, lane = threadIdx.x & 31;
    float s = 0.f; int c = 0;
    for (int t = lane; t < T; t += 32) {
        s += g_probs[(size_t)t * E + e];
        c += (g_top1[t] == e) ? 1 : 0;
    }
    #pragma unroll
    for (int o = 16; o; o >>= 1) {
        s += __shfl_xor_sync(0xffffffffu, s, o);
        c += __shfl_xor_sync(0xffffffffu, c, o);
    }
    __shared__ float part[E];
    if (lane == 0) part[e] = (s / (float)T) * ((float)c / (float)T);
    __syncthreads();
    if (threadIdx.x == 0) {
        float a = 0.f;
        for (int i = 0; i < E; i++) a += part[i];
        *out_aux = a * (float)E * AUX_COEF;
    }
}

// ---------------- launch ----------------
extern "C" void kernel_launch(void* const* d_in, const int* in_sizes, int n_in,
                              void* d_out, int out_size) {
    const float* x  = (const float*)d_in[0];
    const float* Wr = (const float*)d_in[1];
    const float* br = (const float*)d_in[2];
    const float* Wg = (const float*)d_in[3];
    const float* Wu = (const float*)d_in[4];
    const float* Wd = (const float*)d_in[5];
    float* out = (float*)d_out;

    router_kernel<<<T, 256>>>(x, Wr, br);
    dispatch_kernel<<<1, 1024>>>();
    gather_kernel<<<T * KSEL, 256>>>(x);

    dim3 gu_grid(F / BN, CAP / BM, E);
    gu_kernel<<<gu_grid, 256>>>(Wg, Wu);

    dim3 dn_grid(H / BN, CAP / BM, E);
    down_kernel<<<dn_grid, 256>>>(Wd);

    combine_kernel<<<T, 256>>>(out);

    if (out_size > T * H)
        aux_kernel<<<1, 1024>>>(out + (size_t)T * H);
}

// round 3
// speedup vs baseline: 4.6144x; 4.6144x over previous
#include <cuda_runtime.h>
#include <cstdint>

// ---------------- static problem config ----------------
#define T 4096
#define H 1024
#define F 2048
#define E 32
#define KSEL 2
#define CAP 512
#define AUX_COEF 0.01f

// ---------------- device scratch ----------------
__device__ float g_probs[T * E];
__device__ int   g_top1[T];
__device__ int   g_route_e[T * KSEL];
__device__ float g_route_w[T * KSEL];
__device__ int   g_route_pos[T * KSEL];
__device__ int   g_route_keep[T * KSEL];
__device__ int   g_count[E];
__device__ float g_buf[(size_t)E * CAP * H];
__device__ float g_hid[(size_t)E * CAP * F];
__device__ float g_y[(size_t)E * CAP * H];

// ---------------- helpers ----------------
__device__ __forceinline__ uint32_t smem_u32(const void* p) {
    uint32_t a;
    asm("{ .reg .u64 t; cvta.to.shared.u64 t, %1; cvt.u32.u64 %0, t; }" : "=r"(a) : "l"(p));
    return a;
}
__device__ __forceinline__ uint32_t f2tf(float v) {
    uint32_t r; asm("cvt.rna.tf32.f32 %0, %1;" : "=r"(r) : "f"(v)); return r;
}
#define STS128(ad, a0, a1, a2, a3) \
    asm volatile("st.shared.v4.b32 [%0], {%1,%2,%3,%4};" :: "r"(ad), "r"(a0), "r"(a1), "r"(a2), "r"(a3) : "memory")
#define LDSM4(r0, r1, r2, r3, ad) \
    asm volatile("ldmatrix.sync.aligned.m8n8.x4.shared.b16 {%0,%1,%2,%3}, [%4];" \
        : "=r"(r0), "=r"(r1), "=r"(r2), "=r"(r3) : "r"(ad))
#define MMA_TF32(d, a, b0v, b1v) \
    asm volatile("mma.sync.aligned.m16n8k8.row.col.f32.tf32.tf32.f32 " \
        "{%0,%1,%2,%3}, {%4,%5,%6,%7}, {%8,%9}, {%0,%1,%2,%3};" \
        : "+f"(d[0]), "+f"(d[1]), "+f"(d[2]), "+f"(d[3]) \
        : "r"(a[0]), "r"(a[1]), "r"(a[2]), "r"(a[3]), "r"(b0v), "r"(b1v))

// ---------------- router ----------------
__global__ void router_kernel(const float* __restrict__ x,
                              const float* __restrict__ Wr,
                              const float* __restrict__ br) {
    int t = blockIdx.x;
    __shared__ float xs[H];
    __shared__ float sl[E];
    int tid = threadIdx.x;
    for (int h = tid; h < H; h += 256) xs[h] = x[(size_t)t * H + h];
    __syncthreads();
    int e = tid >> 3, r = tid & 7;
    float acc = 0.f;
    const float* w = Wr + (size_t)e * H;
    for (int h = r; h < H; h += 8) acc += xs[h] * w[h];
    acc += __shfl_down_sync(0xffffffffu, acc, 4, 8);
    acc += __shfl_down_sync(0xffffffffu, acc, 2, 8);
    acc += __shfl_down_sync(0xffffffffu, acc, 1, 8);
    if (r == 0) sl[e] = acc + br[e];
    __syncthreads();
    if (tid < 32) {
        float l = sl[tid];
        float m = l;
        #pragma unroll
        for (int o = 16; o; o >>= 1) m = fmaxf(m, __shfl_xor_sync(0xffffffffu, m, o));
        float p = __expf(l - m);
        float s = p;
        #pragma unroll
        for (int o = 16; o; o >>= 1) s += __shfl_xor_sync(0xffffffffu, s, o);
        p = p / s;
        g_probs[(size_t)t * E + tid] = p;
        float p1 = p; int i1 = tid;
        #pragma unroll
        for (int o = 16; o; o >>= 1) {
            float op = __shfl_xor_sync(0xffffffffu, p1, o);
            int   oi = __shfl_xor_sync(0xffffffffu, i1, o);
            if (op > p1 || (op == p1 && oi < i1)) { p1 = op; i1 = oi; }
        }
        float pm = (tid == i1) ? -1.f : p;
        float p2 = pm; int i2 = tid;
        #pragma unroll
        for (int o = 16; o; o >>= 1) {
            float op = __shfl_xor_sync(0xffffffffu, p2, o);
            int   oi = __shfl_xor_sync(0xffffffffu, i2, o);
            if (op > p2 || (op == p2 && oi < i2)) { p2 = op; i2 = oi; }
        }
        if (tid == 0) {
            g_top1[t] = i1;
            float mx = fmaxf(p1, p2);
            float e1 = __expf(p1 - mx), e2 = __expf(p2 - mx);
            float inv = 1.f / (e1 + e2);
            g_route_e[2 * t]     = i1; g_route_w[2 * t]     = e1 * inv;
            g_route_e[2 * t + 1] = i2; g_route_w[2 * t + 1] = e2 * inv;
        }
    }
}

// ---------------- dispatch ----------------
__global__ void dispatch_kernel() {
    __shared__ int se[T * KSEL];
    int tid = threadIdx.x;
    for (int i = tid; i < T * KSEL; i += 1024) se[i] = g_route_e[i];
    __syncthreads();
    int warp = tid >> 5, lane = tid & 31;
    int base = 0;
    for (int c = 0; c < T * KSEL; c += 32) {
        int e = se[c + lane];
        unsigned m = __ballot_sync(0xffffffffu, e == warp);
        if (e == warp) {
            int pos = base + __popc(m & ((1u << lane) - 1u));
            g_route_pos[c + lane]  = pos;
            g_route_keep[c + lane] = (pos < CAP) ? 1 : 0;
        }
        base += __popc(m);
    }
    if (lane == 0) g_count[warp] = (base < CAP) ? base : CAP;
}

// ---------------- gather ----------------
__global__ void gather_kernel(const float* __restrict__ x) {
    int i = blockIdx.x;
    if (!g_route_keep[i]) return;
    int t = i >> 1;
    int e = g_route_e[i], pos = g_route_pos[i];
    float* dst = g_buf + ((size_t)e * CAP + pos) * H;
    const float* src = x + (size_t)t * H;
    for (int h = threadIdx.x; h < H; h += 256) dst[h] = src[h];
}

// ---------------- tf32 mma.sync GEMMs ----------------
// Block 128x128, KC=32, 8 warps (2 in M x 4 in N), warp tile 64x32.
// Smem tiles: A [m][k] row-major 128B rows, B [n][k] (transposed) 128B rows,
// both with 128B swizzle: chunk16(k) ^= (row & 7).
#define KC 32
#define TILE_BYTES 16384
#define GU_STAGE (3 * TILE_BYTES)
#define DN_STAGE (2 * TILE_BYTES)

__global__ void __launch_bounds__(256, 1) gu_mma(const float* __restrict__ Wg,
                                                 const float* __restrict__ Wu) {
    extern __shared__ char smem[];
    int e = blockIdx.z, cnt = g_count[e];
    int m0 = blockIdx.y * 128;
    if (m0 >= cnt) return;
    int n0 = blockIdx.x * 128;
    uint32_t sbuf = (smem_u32(smem) + 127u) & ~127u;

    int tid = threadIdx.x, lane = tid & 31, wid = tid >> 5;
    int wm = wid >> 2, wn = wid & 3;

    const float* A = g_buf + (size_t)e * CAP * H;
    const float* G = Wg + (size_t)e * H * F;
    const float* U = Wu + (size_t)e * H * F;

    // staging indices
    int t8 = tid & 7, rw = tid >> 3;        // A: k-quad, row(+p*32)
    int bn = tid & 127, kh = tid >> 7;      // B: col n, k-half

    // ldmatrix address components
    uint32_t a_row = wm * 64 + ((lane >> 3) & 1) * 8 + (lane & 7);
    uint32_t a_sw  = (a_row & 7) * 16;
    uint32_t a_cb  = (lane >> 4) * 16;
    uint32_t b_rl  = wn * 32 + (lane >> 4) * 8 + (lane & 7);  // +jj*16
    uint32_t b_sw  = (lane & 7) * 16;
    uint32_t b_cb  = ((lane >> 3) & 1) * 16;

    float accG[4][4][4] = {};
    float accU[4][4][4] = {};
    float4 ra[4];
    float rg[16], ru[16];

    const int NS = H / KC;
    // prologue load stage 0
    {
        #pragma unroll
        for (int p = 0; p < 4; p++) {
            int gm = m0 + rw + p * 32;
            ra[p] = (gm < cnt) ? *(const float4*)(A + (size_t)gm * H + t8 * 4)
                               : make_float4(0.f, 0.f, 0.f, 0.f);
        }
        const float* Gp = G + (size_t)0 * F + n0 + bn;
        const float* Up = U + (size_t)0 * F + n0 + bn;
        #pragma unroll
        for (int i = 0; i < 4; i++)
            #pragma unroll
            for (int kk = 0; kk < 4; kk++) {
                rg[i * 4 + kk] = Gp[(size_t)(kh * 16 + i * 4 + kk) * F];
                ru[i * 4 + kk] = Up[(size_t)(kh * 16 + i * 4 + kk) * F];
            }
    }
    // store stage 0
    {
        uint32_t SA = sbuf, SG = SA + TILE_BYTES, SU = SG + TILE_BYTES;
        #pragma unroll
        for (int p = 0; p < 4; p++) {
            int row = rw + p * 32;
            STS128(SA + row * 128 + ((t8 * 16) ^ ((row & 7) * 16)),
                   f2tf(ra[p].x), f2tf(ra[p].y), f2tf(ra[p].z), f2tf(ra[p].w));
        }
        #pragma unroll
        for (int i = 0; i < 4; i++) {
            int kb = kh * 16 + i * 4;
            uint32_t off = bn * 128 + ((kb * 4) ^ ((bn & 7) * 16));
            STS128(SG + off, f2tf(rg[i*4+0]), f2tf(rg[i*4+1]), f2tf(rg[i*4+2]), f2tf(rg[i*4+3]));
            STS128(SU + off, f2tf(ru[i*4+0]), f2tf(ru[i*4+1]), f2tf(ru[i*4+2]), f2tf(ru[i*4+3]));
        }
    }
    __syncthreads();

    for (int s = 0; s < NS; s++) {
        // prefetch next stage
        if (s + 1 < NS) {
            int k0 = (s + 1) * KC;
            #pragma unroll
            for (int p = 0; p < 4; p++) {
                int gm = m0 + rw + p * 32;
                ra[p] = (gm < cnt) ? *(const float4*)(A + (size_t)gm * H + k0 + t8 * 4)
                                   : make_float4(0.f, 0.f, 0.f, 0.f);
            }
            const float* Gp = G + (size_t)k0 * F + n0 + bn;
            const float* Up = U + (size_t)k0 * F + n0 + bn;
            #pragma unroll
            for (int i = 0; i < 4; i++)
                #pragma unroll
                for (int kk = 0; kk < 4; kk++) {
                    rg[i * 4 + kk] = Gp[(size_t)(kh * 16 + i * 4 + kk) * F];
                    ru[i * 4 + kk] = Up[(size_t)(kh * 16 + i * 4 + kk) * F];
                }
        }
        // compute from buffer s&1
        {
            uint32_t SA = sbuf + (s & 1) * GU_STAGE;
            uint32_t SG = SA + TILE_BYTES, SU = SG + TILE_BYTES;
            #pragma unroll
            for (int ks = 0; ks < 4; ks++) {
                uint32_t a[4][4];
                #pragma unroll
                for (int i = 0; i < 4; i++) {
                    uint32_t ad = SA + (a_row + i * 16) * 128 + ((ks * 32 + a_cb) ^ a_sw);
                    LDSM4(a[i][0], a[i][1], a[i][2], a[i][3], ad);
                }
                uint32_t bg[2][4], bu[2][4];
                #pragma unroll
                for (int jj = 0; jj < 2; jj++) {
                    uint32_t nr = b_rl + jj * 16;
                    uint32_t off = nr * 128 + ((ks * 32 + b_cb) ^ b_sw);
                    LDSM4(bg[jj][0], bg[jj][1], bg[jj][2], bg[jj][3], SG + off);
                    LDSM4(bu[jj][0], bu[jj][1], bu[jj][2], bu[jj][3], SU + off);
                }
                #pragma unroll
                for (int i = 0; i < 4; i++)
                    #pragma unroll
                    for (int j = 0; j < 4; j++) {
                        MMA_TF32(accG[i][j], a[i], bg[j >> 1][(j & 1) * 2], bg[j >> 1][(j & 1) * 2 + 1]);
                        MMA_TF32(accU[i][j], a[i], bu[j >> 1][(j & 1) * 2], bu[j >> 1][(j & 1) * 2 + 1]);
                    }
            }
        }
        // store next stage
        if (s + 1 < NS) {
            uint32_t SA = sbuf + ((s + 1) & 1) * GU_STAGE;
            uint32_t SG = SA + TILE_BYTES, SU = SG + TILE_BYTES;
            #pragma unroll
            for (int p = 0; p < 4; p++) {
                int row = rw + p * 32;
                STS128(SA + row * 128 + ((t8 * 16) ^ ((row & 7) * 16)),
                       f2tf(ra[p].x), f2tf(ra[p].y), f2tf(ra[p].z), f2tf(ra[p].w));
            }
            #pragma unroll
            for (int i = 0; i < 4; i++) {
                int kb = kh * 16 + i * 4;
                uint32_t off = bn * 128 + ((kb * 4) ^ ((bn & 7) * 16));
                STS128(SG + off, f2tf(rg[i*4+0]), f2tf(rg[i*4+1]), f2tf(rg[i*4+2]), f2tf(rg[i*4+3]));
                STS128(SU + off, f2tf(ru[i*4+0]), f2tf(ru[i*4+1]), f2tf(ru[i*4+2]), f2tf(ru[i*4+3]));
            }
        }
        __syncthreads();
    }

    // epilogue: silu(g)*u
    float* Hd = g_hid + (size_t)e * CAP * F;
    int r0 = m0 + wm * 64 + (lane >> 2);
    int c0 = n0 + wn * 32 + (lane & 3) * 2;
    #pragma unroll
    for (int i = 0; i < 4; i++) {
        #pragma unroll
        for (int j = 0; j < 4; j++) {
            int row = r0 + i * 16;
            int col = c0 + j * 8;
            if (row < cnt) {
                float g0 = accG[i][j][0], g1 = accG[i][j][1];
                float2 v = make_float2((g0 / (1.f + __expf(-g0))) * accU[i][j][0],
                                       (g1 / (1.f + __expf(-g1))) * accU[i][j][1]);
                *(float2*)(Hd + (size_t)row * F + col) = v;
            }
            if (row + 8 < cnt) {
                float g2 = accG[i][j][2], g3 = accG[i][j][3];
                float2 v = make_float2((g2 / (1.f + __expf(-g2))) * accU[i][j][2],
                                       (g3 / (1.f + __expf(-g3))) * accU[i][j][3]);
                *(float2*)(Hd + (size_t)(row + 8) * F + col) = v;
            }
        }
    }
}

__global__ void __launch_bounds__(256, 1) down_mma(const float* __restrict__ Wd) {
    extern __shared__ char smem[];
    int e = blockIdx.z, cnt = g_count[e];
    int m0 = blockIdx.y * 128;
    if (m0 >= cnt) return;
    int n0 = blockIdx.x * 128;
    uint32_t sbuf = (smem_u32(smem) + 127u) & ~127u;

    int tid = threadIdx.x, lane = tid & 31, wid = tid >> 5;
    int wm = wid >> 2, wn = wid & 3;

    const float* A = g_hid + (size_t)e * CAP * F;
    const float* B = Wd + (size_t)e * F * H;

    int t8 = tid & 7, rw = tid >> 3;
    int bn = tid & 127, kh = tid >> 7;

    uint32_t a_row = wm * 64 + ((lane >> 3) & 1) * 8 + (lane & 7);
    uint32_t a_sw  = (a_row & 7) * 16;
    uint32_t a_cb  = (lane >> 4) * 16;
    uint32_t b_rl  = wn * 32 + (lane >> 4) * 8 + (lane & 7);
    uint32_t b_sw  = (lane & 7) * 16;
    uint32_t b_cb  = ((lane >> 3) & 1) * 16;

    float accD[4][4][4] = {};
    float4 ra[4];
    float rb[16];

    const int NS = F / KC;
    {
        #pragma unroll
        for (int p = 0; p < 4; p++) {
            int gm = m0 + rw + p * 32;
            ra[p] = (gm < cnt) ? *(const float4*)(A + (size_t)gm * F + t8 * 4)
                               : make_float4(0.f, 0.f, 0.f, 0.f);
        }
        const float* Bp = B + n0 + bn;
        #pragma unroll
        for (int i = 0; i < 4; i++)
            #pragma unroll
            for (int kk = 0; kk < 4; kk++)
                rb[i * 4 + kk] = Bp[(size_t)(kh * 16 + i * 4 + kk) * H];
    }
    {
        uint32_t SA = sbuf, SB = SA + TILE_BYTES;
        #pragma unroll
        for (int p = 0; p < 4; p++) {
            int row = rw + p * 32;
            STS128(SA + row * 128 + ((t8 * 16) ^ ((row & 7) * 16)),
                   f2tf(ra[p].x), f2tf(ra[p].y), f2tf(ra[p].z), f2tf(ra[p].w));
        }
        #pragma unroll
        for (int i = 0; i < 4; i++) {
            int kb = kh * 16 + i * 4;
            uint32_t off = bn * 128 + ((kb * 4) ^ ((bn & 7) * 16));
            STS128(SB + off, f2tf(rb[i*4+0]), f2tf(rb[i*4+1]), f2tf(rb[i*4+2]), f2tf(rb[i*4+3]));
        }
    }
    __syncthreads();

    for (int s = 0; s < NS; s++) {
        if (s + 1 < NS) {
            int k0 = (s + 1) * KC;
            #pragma unroll
            for (int p = 0; p < 4; p++) {
                int gm = m0 + rw + p * 32;
                ra[p] = (gm < cnt) ? *(const float4*)(A + (size_t)gm * F + k0 + t8 * 4)
                                   : make_float4(0.f, 0.f, 0.f, 0.f);
            }
            const float* Bp = B + (size_t)k0 * H + n0 + bn;
            #pragma unroll
            for (int i = 0; i < 4; i++)
                #pragma unroll
                for (int kk = 0; kk < 4; kk++)
                    rb[i * 4 + kk] = Bp[(size_t)(kh * 16 + i * 4 + kk) * H];
        }
        {
            uint32_t SA = sbuf + (s & 1) * DN_STAGE;
            uint32_t SB = SA + TILE_BYTES;
            #pragma unroll
            for (int ks = 0; ks < 4; ks++) {
                uint32_t a[4][4];
                #pragma unroll
                for (int i = 0; i < 4; i++) {
                    uint32_t ad = SA + (a_row + i * 16) * 128 + ((ks * 32 + a_cb) ^ a_sw);
                    LDSM4(a[i][0], a[i][1], a[i][2], a[i][3], ad);
                }
                uint32_t bb[2][4];
                #pragma unroll
                for (int jj = 0; jj < 2; jj++) {
                    uint32_t nr = b_rl + jj * 16;
                    uint32_t off = nr * 128 + ((ks * 32 + b_cb) ^ b_sw);
                    LDSM4(bb[jj][0], bb[jj][1], bb[jj][2], bb[jj][3], SB + off);
                }
                #pragma unroll
                for (int i = 0; i < 4; i++)
                    #pragma unroll
                    for (int j = 0; j < 4; j++)
                        MMA_TF32(accD[i][j], a[i], bb[j >> 1][(j & 1) * 2], bb[j >> 1][(j & 1) * 2 + 1]);
            }
        }
        if (s + 1 < NS) {
            uint32_t SA = sbuf + ((s + 1) & 1) * DN_STAGE;
            uint32_t SB = SA + TILE_BYTES;
            #pragma unroll
            for (int p = 0; p < 4; p++) {
                int row = rw + p * 32;
                STS128(SA + row * 128 + ((t8 * 16) ^ ((row & 7) * 16)),
                       f2tf(ra[p].x), f2tf(ra[p].y), f2tf(ra[p].z), f2tf(ra[p].w));
            }
            #pragma unroll
            for (int i = 0; i < 4; i++) {
                int kb = kh * 16 + i * 4;
                uint32_t off = bn * 128 + ((kb * 4) ^ ((bn & 7) * 16));
                STS128(SB + off, f2tf(rb[i*4+0]), f2tf(rb[i*4+1]), f2tf(rb[i*4+2]), f2tf(rb[i*4+3]));
            }
        }
        __syncthreads();
    }

    float* Y = g_y + (size_t)e * CAP * H;
    int r0 = m0 + wm * 64 + (lane >> 2);
    int c0 = n0 + wn * 32 + (lane & 3) * 2;
    #pragma unroll
    for (int i = 0; i < 4; i++) {
        #pragma unroll
        for (int j = 0; j < 4; j++) {
            int row = r0 + i * 16;
            int col = c0 + j * 8;
            if (row < cnt)
                *(float2*)(Y + (size_t)row * H + col) = make_float2(accD[i][j][0], accD[i][j][1]);
            if (row + 8 < cnt)
                *(float2*)(Y + (size_t)(row + 8) * H + col) = make_float2(accD[i][j][2], accD[i][j][3]);
        }
    }
}

// ---------------- combine ----------------
__global__ void combine_kernel(float* __restrict__ out) {
    int t = blockIdx.x;
    int i0 = 2 * t, i1 = 2 * t + 1;
    int e0 = g_route_e[i0], e1 = g_route_e[i1];
    int k0 = g_route_keep[i0], k1 = g_route_keep[i1];
    int p0 = k0 ? g_route_pos[i0] : 0;
    int p1 = k1 ? g_route_pos[i1] : 0;
    float w0 = k0 ? g_route_w[i0] : 0.f;
    float w1 = k1 ? g_route_w[i1] : 0.f;
    const float* y0 = g_y + ((size_t)e0 * CAP + p0) * H;
    const float* y1 = g_y + ((size_t)e1 * CAP + p1) * H;
    float* o = out + (size_t)t * H;
    for (int h = threadIdx.x; h < H; h += 256)
        o[h] = w0 * y0[h] + w1 * y1[h];
}

// ---------------- aux loss ----------------
__global__ void aux_kernel(float* __restrict__ out_aux) {
    int e = threadIdx.x >> 5, lane = threadIdx.x & 31;
    float s = 0.f; int c = 0;
    for (int t = lane; t < T; t += 32) {
        s += g_probs[(size_t)t * E + e];
        c += (g_top1[t] == e) ? 1 : 0;
    }
    #pragma unroll
    for (int o = 16; o; o >>= 1) {
        s += __shfl_xor_sync(0xffffffffu, s, o);
        c += __shfl_xor_sync(0xffffffffu, c, o);
    }
    __shared__ float part[E];
    if (lane == 0) part[e] = (s / (float)T) * ((float)c / (float)T);
    __syncthreads();
    if (threadIdx.x == 0) {
        float a = 0.f;
        for (int i = 0; i < E; i++) a += part[i];
        *out_aux = a * (float)E * AUX_COEF;
    }
}

// ---------------- launch ----------------
extern "C" void kernel_launch(void* const* d_in, const int* in_sizes, int n_in,
                              void* d_out, int out_size) {
    const float* x  = (const float*)d_in[0];
    const float* Wr = (const float*)d_in[1];
    const float* br = (const float*)d_in[2];
    const float* Wg = (const float*)d_in[3];
    const float* Wu = (const float*)d_in[4];
    const float* Wd = (const float*)d_in[5];
    float* out = (float*)d_out;

    cudaFuncSetAttribute(gu_mma, cudaFuncAttributeMaxDynamicSharedMemorySize, 128 + 2 * GU_STAGE);
    cudaFuncSetAttribute(down_mma, cudaFuncAttributeMaxDynamicSharedMemorySize, 128 + 2 * DN_STAGE);

    router_kernel<<<T, 256>>>(x, Wr, br);
    dispatch_kernel<<<1, 1024>>>();
    gather_kernel<<<T * KSEL, 256>>>(x);

    dim3 gu_grid(F / 128, CAP / 128, E);
    gu_mma<<<gu_grid, 256, 128 + 2 * GU_STAGE>>>(Wg, Wu);

    dim3 dn_grid(H / 128, CAP / 128, E);
    down_mma<<<dn_grid, 256, 128 + 2 * DN_STAGE>>>(Wd);

    combine_kernel<<<T, 256>>>(out);

    if (out_size > T * H)
        aux_kernel<<<1, 1024>>>(out + (size_t)T * H);
}

// round 4
// speedup vs baseline: 4.6671x; 1.0114x over previous
#include <cuda_runtime.h>
#include <cstdint>

// ---------------- static problem config ----------------
#define T 4096
#define H 1024
#define F 2048
#define E 32
#define KSEL 2
#define CAP 512
#define AUX_COEF 0.01f

// ---------------- device scratch ----------------
__device__ float g_probs[T * E];
__device__ int   g_top1[T];
__device__ int   g_route_e[T * KSEL];
__device__ float g_route_w[T * KSEL];
__device__ int   g_route_pos[T * KSEL];
__device__ int   g_route_keep[T * KSEL];
__device__ int   g_count[E];
__device__ float g_buf[(size_t)E * CAP * H];   // pre-rounded to tf32 bits
__device__ float g_hid[(size_t)E * CAP * F];   // pre-rounded to tf32 bits
__device__ float g_y[(size_t)E * CAP * H];

// ---------------- helpers ----------------
__device__ __forceinline__ uint32_t smem_u32(const void* p) {
    uint32_t a;
    asm("{ .reg .u64 t; cvta.to.shared.u64 t, %1; cvt.u32.u64 %0, t; }" : "=r"(a) : "l"(p));
    return a;
}
__device__ __forceinline__ uint32_t f2tf(float v) {
    uint32_t r; asm("cvt.rna.tf32.f32 %0, %1;" : "=r"(r) : "f"(v)); return r;
}
#define STS128(ad, a0, a1, a2, a3) \
    asm volatile("st.shared.v4.b32 [%0], {%1,%2,%3,%4};" :: "r"(ad), "r"(a0), "r"(a1), "r"(a2), "r"(a3) : "memory")
#define LDSM4(r0, r1, r2, r3, ad) \
    asm volatile("ldmatrix.sync.aligned.m8n8.x4.shared.b16 {%0,%1,%2,%3}, [%4];" \
        : "=r"(r0), "=r"(r1), "=r"(r2), "=r"(r3) : "r"(ad))
#define MMA_TF32(d, a0v, a1v, a2v, a3v, b0v, b1v) \
    asm volatile("mma.sync.aligned.m16n8k8.row.col.f32.tf32.tf32.f32 " \
        "{%0,%1,%2,%3}, {%4,%5,%6,%7}, {%8,%9}, {%0,%1,%2,%3};" \
        : "+f"(d[0]), "+f"(d[1]), "+f"(d[2]), "+f"(d[3]) \
        : "r"(a0v), "r"(a1v), "r"(a2v), "r"(a3v), "r"(b0v), "r"(b1v))

// ---------------- router ----------------
__global__ void router_kernel(const float* __restrict__ x,
                              const float* __restrict__ Wr,
                              const float* __restrict__ br) {
    int t = blockIdx.x;
    __shared__ float xs[H];
    __shared__ float sl[E];
    int tid = threadIdx.x;
    for (int h = tid; h < H; h += 256) xs[h] = x[(size_t)t * H + h];
    __syncthreads();
    int e = tid >> 3, r = tid & 7;
    float acc = 0.f;
    const float* w = Wr + (size_t)e * H;
    for (int h = r; h < H; h += 8) acc += xs[h] * w[h];
    acc += __shfl_down_sync(0xffffffffu, acc, 4, 8);
    acc += __shfl_down_sync(0xffffffffu, acc, 2, 8);
    acc += __shfl_down_sync(0xffffffffu, acc, 1, 8);
    if (r == 0) sl[e] = acc + br[e];
    __syncthreads();
    if (tid < 32) {
        float l = sl[tid];
        float m = l;
        #pragma unroll
        for (int o = 16; o; o >>= 1) m = fmaxf(m, __shfl_xor_sync(0xffffffffu, m, o));
        float p = __expf(l - m);
        float s = p;
        #pragma unroll
        for (int o = 16; o; o >>= 1) s += __shfl_xor_sync(0xffffffffu, s, o);
        p = p / s;
        g_probs[(size_t)t * E + tid] = p;
        float p1 = p; int i1 = tid;
        #pragma unroll
        for (int o = 16; o; o >>= 1) {
            float op = __shfl_xor_sync(0xffffffffu, p1, o);
            int   oi = __shfl_xor_sync(0xffffffffu, i1, o);
            if (op > p1 || (op == p1 && oi < i1)) { p1 = op; i1 = oi; }
        }
        float pm = (tid == i1) ? -1.f : p;
        float p2 = pm; int i2 = tid;
        #pragma unroll
        for (int o = 16; o; o >>= 1) {
            float op = __shfl_xor_sync(0xffffffffu, p2, o);
            int   oi = __shfl_xor_sync(0xffffffffu, i2, o);
            if (op > p2 || (op == p2 && oi < i2)) { p2 = op; i2 = oi; }
        }
        if (tid == 0) {
            g_top1[t] = i1;
            float mx = fmaxf(p1, p2);
            float e1 = __expf(p1 - mx), e2 = __expf(p2 - mx);
            float inv = 1.f / (e1 + e2);
            g_route_e[2 * t]     = i1; g_route_w[2 * t]     = e1 * inv;
            g_route_e[2 * t + 1] = i2; g_route_w[2 * t + 1] = e2 * inv;
        }
    }
}

// ---------------- dispatch ----------------
__global__ void dispatch_kernel() {
    __shared__ int se[T * KSEL];
    int tid = threadIdx.x;
    for (int i = tid; i < T * KSEL; i += 1024) se[i] = g_route_e[i];
    __syncthreads();
    int warp = tid >> 5, lane = tid & 31;
    int base = 0;
    for (int c = 0; c < T * KSEL; c += 32) {
        int e = se[c + lane];
        unsigned m = __ballot_sync(0xffffffffu, e == warp);
        if (e == warp) {
            int pos = base + __popc(m & ((1u << lane) - 1u));
            g_route_pos[c + lane]  = pos;
            g_route_keep[c + lane] = (pos < CAP) ? 1 : 0;
        }
        base += __popc(m);
    }
    if (lane == 0) g_count[warp] = (base < CAP) ? base : CAP;
}

// ---------------- gather (pre-rounds activations to tf32 bits) ----------------
__global__ void gather_kernel(const float* __restrict__ x) {
    int i = blockIdx.x;
    if (!g_route_keep[i]) return;
    int t = i >> 1;
    int e = g_route_e[i], pos = g_route_pos[i];
    float* dst = g_buf + ((size_t)e * CAP + pos) * H;
    const float* src = x + (size_t)t * H;
    int h = threadIdx.x * 4;
    float4 v = *(const float4*)(src + h);
    uint4 o;
    o.x = f2tf(v.x); o.y = f2tf(v.y); o.z = f2tf(v.z); o.w = f2tf(v.w);
    *(uint4*)(dst + h) = o;
}

// ---------------- tf32 mma.sync GEMMs ----------------
// Block 128x128, KC=32, 16 warps (4m x 4n), warp tile 32x32.
// Smem: A [m][k] 128B rows, B [n][k] 128B rows, swizzle chunk ^= (row&7)*16.
#define KC 32
#define TILE_BYTES 16384
#define GU_STAGE (3 * TILE_BYTES)
#define DN_STAGE (2 * TILE_BYTES)

__global__ void __launch_bounds__(512, 1) gu_mma(const float* __restrict__ Wg,
                                                 const float* __restrict__ Wu) {
    extern __shared__ char smem[];
    int e = blockIdx.z, cnt = g_count[e];
    int m0 = blockIdx.y * 128;
    if (m0 >= cnt) return;
    int n0 = blockIdx.x * 128;
    uint32_t sbuf = (smem_u32(smem) + 127u) & ~127u;

    int tid = threadIdx.x, lane = tid & 31, wid = tid >> 5;
    int wm = wid >> 2, wn = wid & 3;

    const float* A = g_buf + (size_t)e * CAP * H;
    const float* G = Wg + (size_t)e * H * F;
    const float* U = Wu + (size_t)e * H * F;

    // staging indices
    int t8 = tid & 7, rw = tid >> 3;        // A: k-chunk, base row (0..63), +p*64
    int bn = tid & 127, kq = tid >> 7;      // B: col n, k-quad (0..3)

    // ldmatrix address components
    uint32_t a_row = wm * 32 + ((lane >> 3) & 1) * 8 + (lane & 7);
    uint32_t a_sw  = (a_row & 7) * 16;
    uint32_t a_cb  = (lane >> 4) * 16;
    uint32_t b_rl  = wn * 32 + (lane >> 4) * 8 + (lane & 7);
    uint32_t b_sw  = (lane & 7) * 16;
    uint32_t b_cb  = ((lane >> 3) & 1) * 16;

    float accG[2][4][4] = {};
    float accU[2][4][4] = {};
    uint4 ra[2];
    float rg[8], ru[8];

    const int NS = H / KC;
    // prologue: load + store stage 0
    {
        #pragma unroll
        for (int p = 0; p < 2; p++) {
            int gm = m0 + rw + p * 64;
            ra[p] = (gm < cnt) ? *(const uint4*)(A + (size_t)gm * H + t8 * 4)
                               : make_uint4(0u, 0u, 0u, 0u);
        }
        const float* Gp = G + (size_t)(kq * 8) * F + n0 + bn;
        const float* Up = U + (size_t)(kq * 8) * F + n0 + bn;
        #pragma unroll
        for (int kk = 0; kk < 8; kk++) {
            rg[kk] = Gp[(size_t)kk * F];
            ru[kk] = Up[(size_t)kk * F];
        }
        uint32_t SA = sbuf, SG = SA + TILE_BYTES, SU = SG + TILE_BYTES;
        #pragma unroll
        for (int p = 0; p < 2; p++) {
            int row = rw + p * 64;
            STS128(SA + row * 128 + ((t8 * 16) ^ ((row & 7) * 16)), ra[p].x, ra[p].y, ra[p].z, ra[p].w);
        }
        #pragma unroll
        for (int g = 0; g < 2; g++) {
            uint32_t off = bn * 128 + (((kq * 32) + g * 16) ^ ((bn & 7) * 16));
            STS128(SG + off, f2tf(rg[g*4+0]), f2tf(rg[g*4+1]), f2tf(rg[g*4+2]), f2tf(rg[g*4+3]));
            STS128(SU + off, f2tf(ru[g*4+0]), f2tf(ru[g*4+1]), f2tf(ru[g*4+2]), f2tf(ru[g*4+3]));
        }
    }
    __syncthreads();

    for (int s = 0; s < NS; s++) {
        if (s + 1 < NS) {
            int k0 = (s + 1) * KC;
            #pragma unroll
            for (int p = 0; p < 2; p++) {
                int gm = m0 + rw + p * 64;
                ra[p] = (gm < cnt) ? *(const uint4*)(A + (size_t)gm * H + k0 + t8 * 4)
                                   : make_uint4(0u, 0u, 0u, 0u);
            }
            const float* Gp = G + (size_t)(k0 + kq * 8) * F + n0 + bn;
            const float* Up = U + (size_t)(k0 + kq * 8) * F + n0 + bn;
            #pragma unroll
            for (int kk = 0; kk < 8; kk++) {
                rg[kk] = Gp[(size_t)kk * F];
                ru[kk] = Up[(size_t)kk * F];
            }
        }
        {
            uint32_t SA = sbuf + (s & 1) * GU_STAGE;
            uint32_t SG = SA + TILE_BYTES, SU = SG + TILE_BYTES;
            #pragma unroll
            for (int ks = 0; ks < 4; ks++) {
                uint32_t a[2][4];
                #pragma unroll
                for (int i = 0; i < 2; i++) {
                    uint32_t ad = SA + (a_row + i * 16) * 128 + ((ks * 32 + a_cb) ^ a_sw);
                    LDSM4(a[i][0], a[i][1], a[i][2], a[i][3], ad);
                }
                uint32_t bg[2][4], bu[2][4];
                #pragma unroll
                for (int jj = 0; jj < 2; jj++) {
                    uint32_t off = (b_rl + jj * 16) * 128 + ((ks * 32 + b_cb) ^ b_sw);
                    LDSM4(bg[jj][0], bg[jj][1], bg[jj][2], bg[jj][3], SG + off);
                    LDSM4(bu[jj][0], bu[jj][1], bu[jj][2], bu[jj][3], SU + off);
                }
                #pragma unroll
                for (int i = 0; i < 2; i++)
                    #pragma unroll
                    for (int j = 0; j < 4; j++) {
                        MMA_TF32(accG[i][j], a[i][0], a[i][1], a[i][2], a[i][3],
                                 bg[j >> 1][(j & 1) * 2], bg[j >> 1][(j & 1) * 2 + 1]);
                        MMA_TF32(accU[i][j], a[i][0], a[i][1], a[i][2], a[i][3],
                                 bu[j >> 1][(j & 1) * 2], bu[j >> 1][(j & 1) * 2 + 1]);
                    }
            }
        }
        if (s + 1 < NS) {
            uint32_t SA = sbuf + ((s + 1) & 1) * GU_STAGE;
            uint32_t SG = SA + TILE_BYTES, SU = SG + TILE_BYTES;
            #pragma unroll
            for (int p = 0; p < 2; p++) {
                int row = rw + p * 64;
                STS128(SA + row * 128 + ((t8 * 16) ^ ((row & 7) * 16)), ra[p].x, ra[p].y, ra[p].z, ra[p].w);
            }
            #pragma unroll
            for (int g = 0; g < 2; g++) {
                uint32_t off = bn * 128 + (((kq * 32) + g * 16) ^ ((bn & 7) * 16));
                STS128(SG + off, f2tf(rg[g*4+0]), f2tf(rg[g*4+1]), f2tf(rg[g*4+2]), f2tf(rg[g*4+3]));
                STS128(SU + off, f2tf(ru[g*4+0]), f2tf(ru[g*4+1]), f2tf(ru[g*4+2]), f2tf(ru[g*4+3]));
            }
        }
        __syncthreads();
    }

    // epilogue: silu(g)*u, pre-rounded to tf32 bits for the down GEMM
    float* Hd = g_hid + (size_t)e * CAP * F;
    int r0 = m0 + wm * 32 + (lane >> 2);
    int c0 = n0 + wn * 32 + (lane & 3) * 2;
    #pragma unroll
    for (int i = 0; i < 2; i++) {
        #pragma unroll
        for (int j = 0; j < 4; j++) {
            int row = r0 + i * 16;
            int col = c0 + j * 8;
            if (row < cnt) {
                float g0 = accG[i][j][0], g1 = accG[i][j][1];
                uint2 v;
                v.x = f2tf((g0 / (1.f + __expf(-g0))) * accU[i][j][0]);
                v.y = f2tf((g1 / (1.f + __expf(-g1))) * accU[i][j][1]);
                *(uint2*)(Hd + (size_t)row * F + col) = v;
            }
            if (row + 8 < cnt) {
                float g2 = accG[i][j][2], g3 = accG[i][j][3];
                uint2 v;
                v.x = f2tf((g2 / (1.f + __expf(-g2))) * accU[i][j][2]);
                v.y = f2tf((g3 / (1.f + __expf(-g3))) * accU[i][j][3]);
                *(uint2*)(Hd + (size_t)(row + 8) * F + col) = v;
            }
        }
    }
}

__global__ void __launch_bounds__(512, 1) down_mma(const float* __restrict__ Wd) {
    extern __shared__ char smem[];
    int e = blockIdx.z, cnt = g_count[e];
    int m0 = blockIdx.y * 128;
    if (m0 >= cnt) return;
    int n0 = blockIdx.x * 128;
    uint32_t sbuf = (smem_u32(smem) + 127u) & ~127u;

    int tid = threadIdx.x, lane = tid & 31, wid = tid >> 5;
    int wm = wid >> 2, wn = wid & 3;

    const float* A = g_hid + (size_t)e * CAP * F;
    const float* B = Wd + (size_t)e * F * H;

    int t8 = tid & 7, rw = tid >> 3;
    int bn = tid & 127, kq = tid >> 7;

    uint32_t a_row = wm * 32 + ((lane >> 3) & 1) * 8 + (lane & 7);
    uint32_t a_sw  = (a_row & 7) * 16;
    uint32_t a_cb  = (lane >> 4) * 16;
    uint32_t b_rl  = wn * 32 + (lane >> 4) * 8 + (lane & 7);
    uint32_t b_sw  = (lane & 7) * 16;
    uint32_t b_cb  = ((lane >> 3) & 1) * 16;

    float accD[2][4][4] = {};
    uint4 ra[2];
    float rb[8];

    const int NS = F / KC;
    {
        #pragma unroll
        for (int p = 0; p < 2; p++) {
            int gm = m0 + rw + p * 64;
            ra[p] = (gm < cnt) ? *(const uint4*)(A + (size_t)gm * F + t8 * 4)
                               : make_uint4(0u, 0u, 0u, 0u);
        }
        const float* Bp = B + (size_t)(kq * 8) * H + n0 + bn;
        #pragma unroll
        for (int kk = 0; kk < 8; kk++) rb[kk] = Bp[(size_t)kk * H];
        uint32_t SA = sbuf, SB = SA + TILE_BYTES;
        #pragma unroll
        for (int p = 0; p < 2; p++) {
            int row = rw + p * 64;
            STS128(SA + row * 128 + ((t8 * 16) ^ ((row & 7) * 16)), ra[p].x, ra[p].y, ra[p].z, ra[p].w);
        }
        #pragma unroll
        for (int g = 0; g < 2; g++) {
            uint32_t off = bn * 128 + (((kq * 32) + g * 16) ^ ((bn & 7) * 16));
            STS128(SB + off, f2tf(rb[g*4+0]), f2tf(rb[g*4+1]), f2tf(rb[g*4+2]), f2tf(rb[g*4+3]));
        }
    }
    __syncthreads();

    for (int s = 0; s < NS; s++) {
        if (s + 1 < NS) {
            int k0 = (s + 1) * KC;
            #pragma unroll
            for (int p = 0; p < 2; p++) {
                int gm = m0 + rw + p * 64;
                ra[p] = (gm < cnt) ? *(const uint4*)(A + (size_t)gm * F + k0 + t8 * 4)
                                   : make_uint4(0u, 0u, 0u, 0u);
            }
            const float* Bp = B + (size_t)(k0 + kq * 8) * H + n0 + bn;
            #pragma unroll
            for (int kk = 0; kk < 8; kk++) rb[kk] = Bp[(size_t)kk * H];
        }
        {
            uint32_t SA = sbuf + (s & 1) * DN_STAGE;
            uint32_t SB = SA + TILE_BYTES;
            #pragma unroll
            for (int ks = 0; ks < 4; ks++) {
                uint32_t a[2][4];
                #pragma unroll
                for (int i = 0; i < 2; i++) {
                    uint32_t ad = SA + (a_row + i * 16) * 128 + ((ks * 32 + a_cb) ^ a_sw);
                    LDSM4(a[i][0], a[i][1], a[i][2], a[i][3], ad);
                }
                uint32_t bb[2][4];
                #pragma unroll
                for (int jj = 0; jj < 2; jj++) {
                    uint32_t off = (b_rl + jj * 16) * 128 + ((ks * 32 + b_cb) ^ b_sw);
                    LDSM4(bb[jj][0], bb[jj][1], bb[jj][2], bb[jj][3], SB + off);
                }
                #pragma unroll
                for (int i = 0; i < 2; i++)
                    #pragma unroll
                    for (int j = 0; j < 4; j++)
                        MMA_TF32(accD[i][j], a[i][0], a[i][1], a[i][2], a[i][3],
                                 bb[j >> 1][(j & 1) * 2], bb[j >> 1][(j & 1) * 2 + 1]);
            }
        }
        if (s + 1 < NS) {
            uint32_t SA = sbuf + ((s + 1) & 1) * DN_STAGE;
            uint32_t SB = SA + TILE_BYTES;
            #pragma unroll
            for (int p = 0; p < 2; p++) {
                int row = rw + p * 64;
                STS128(SA + row * 128 + ((t8 * 16) ^ ((row & 7) * 16)), ra[p].x, ra[p].y, ra[p].z, ra[p].w);
            }
            #pragma unroll
            for (int g = 0; g < 2; g++) {
                uint32_t off = bn * 128 + (((kq * 32) + g * 16) ^ ((bn & 7) * 16));
                STS128(SB + off, f2tf(rb[g*4+0]), f2tf(rb[g*4+1]), f2tf(rb[g*4+2]), f2tf(rb[g*4+3]));
            }
        }
        __syncthreads();
    }

    float* Y = g_y + (size_t)e * CAP * H;
    int r0 = m0 + wm * 32 + (lane >> 2);
    int c0 = n0 + wn * 32 + (lane & 3) * 2;
    #pragma unroll
    for (int i = 0; i < 2; i++) {
        #pragma unroll
        for (int j = 0; j < 4; j++) {
            int row = r0 + i * 16;
            int col = c0 + j * 8;
            if (row < cnt)
                *(float2*)(Y + (size_t)row * H + col) = make_float2(accD[i][j][0], accD[i][j][1]);
            if (row + 8 < cnt)
                *(float2*)(Y + (size_t)(row + 8) * H + col) = make_float2(accD[i][j][2], accD[i][j][3]);
        }
    }
}

// ---------------- combine ----------------
__global__ void combine_kernel(float* __restrict__ out) {
    int t = blockIdx.x;
    int i0 = 2 * t, i1 = 2 * t + 1;
    int e0 = g_route_e[i0], e1 = g_route_e[i1];
    int k0 = g_route_keep[i0], k1 = g_route_keep[i1];
    int p0 = k0 ? g_route_pos[i0] : 0;
    int p1 = k1 ? g_route_pos[i1] : 0;
    float w0 = k0 ? g_route_w[i0] : 0.f;
    float w1 = k1 ? g_route_w[i1] : 0.f;
    const float* y0 = g_y + ((size_t)e0 * CAP + p0) * H;
    const float* y1 = g_y + ((size_t)e1 * CAP + p1) * H;
    float* o = out + (size_t)t * H;
    int h = threadIdx.x * 4;
    float4 a = *(const float4*)(y0 + h);
    float4 b = *(const float4*)(y1 + h);
    float4 r;
    r.x = w0 * a.x + w1 * b.x;
    r.y = w0 * a.y + w1 * b.y;
    r.z = w0 * a.z + w1 * b.z;
    r.w = w0 * a.w + w1 * b.w;
    *(float4*)(o + h) = r;
}

// ---------------- aux loss ----------------
__global__ void aux_kernel(float* __restrict__ out_aux) {
    int e = threadIdx.x >> 5, lane = threadIdx.x & 31;
    float s = 0.f; int c = 0;
    for (int t = lane; t < T; t += 32) {
        s += g_probs[(size_t)t * E + e];
        c += (g_top1[t] == e) ? 1 : 0;
    }
    #pragma unroll
    for (int o = 16; o; o >>= 1) {
        s += __shfl_xor_sync(0xffffffffu, s, o);
        c += __shfl_xor_sync(0xffffffffu, c, o);
    }
    __shared__ float part[E];
    if (lane == 0) part[e] = (s / (float)T) * ((float)c / (float)T);
    __syncthreads();
    if (threadIdx.x == 0) {
        float a = 0.f;
        for (int i = 0; i < E; i++) a += part[i];
        *out_aux = a * (float)E * AUX_COEF;
    }
}

// ---------------- launch ----------------
extern "C" void kernel_launch(void* const* d_in, const int* in_sizes, int n_in,
                              void* d_out, int out_size) {
    const float* x  = (const float*)d_in[0];
    const float* Wr = (const float*)d_in[1];
    const float* br = (const float*)d_in[2];
    const float* Wg = (const float*)d_in[3];
    const float* Wu = (const float*)d_in[4];
    const float* Wd = (const float*)d_in[5];
    float* out = (float*)d_out;

    cudaFuncSetAttribute(gu_mma, cudaFuncAttributeMaxDynamicSharedMemorySize, 128 + 2 * GU_STAGE);
    cudaFuncSetAttribute(down_mma, cudaFuncAttributeMaxDynamicSharedMemorySize, 128 + 2 * DN_STAGE);

    router_kernel<<<T, 256>>>(x, Wr, br);
    dispatch_kernel<<<1, 1024>>>();
    gather_kernel<<<T * KSEL, 256>>>(x);

    dim3 gu_grid(F / 128, CAP / 128, E);
    gu_mma<<<gu_grid, 512, 128 + 2 * GU_STAGE>>>(Wg, Wu);

    dim3 dn_grid(H / 128, CAP / 128, E);
    down_mma<<<dn_grid, 512, 128 + 2 * DN_STAGE>>>(Wd);

    combine_kernel<<<T, 256>>>(out);

    if (out_size > T * H)
        aux_kernel<<<1, 1024>>>(out + (size_t)T * H);
}